// round 15
// baseline (speedup 1.0000x reference)
#include <cuda_runtime.h>
#include <cuda_bf16.h>
#include <cstdint>
#include <cstddef>

// Problem constants
#define BB   2
#define SS   2048
#define DD   1024
#define HH   16
#define HD   64
#define MM   (BB*SS)

// fp32 scratch for V
__device__ float g_v [BB*SS*DD];

// bf16 hi/lo split scratch
__device__ __nv_bfloat16 g_xh [MM*DD], g_xl [MM*DD];
__device__ __nv_bfloat16 g_aoh[MM*DD], g_aol[MM*DD];
__device__ __nv_bfloat16 g_wqh[DD*DD], g_wql[DD*DD];
__device__ __nv_bfloat16 g_wkh[DD*DD], g_wkl[DD*DD];
__device__ __nv_bfloat16 g_wvh[DD*DD], g_wvl[DD*DD];
__device__ __nv_bfloat16 g_woh[DD*DD], g_wol[DD*DD];

// attention operands: q,k [B,H,S,HD]; v transposed [B,H,HD,S]
__device__ __nv_bfloat16 g_qh [MM*DD], g_ql [MM*DD];
__device__ __nv_bfloat16 g_kh [MM*DD], g_kl [MM*DD];
__device__ __nv_bfloat16 g_vth[MM*DD], g_vtl[MM*DD];

// ---------------------------------------------------------------------------
// helpers
// ---------------------------------------------------------------------------
__device__ __forceinline__ uint32_t smem_u32(const void* p) {
    uint32_t a;
    asm("{ .reg .u64 t; cvta.to.shared.u64 t, %1; cvt.u32.u64 %0, t; }"
        : "=r"(a) : "l"(p));
    return a;
}
__device__ __forceinline__ void ldm4(uint32_t& r0, uint32_t& r1, uint32_t& r2,
                                     uint32_t& r3, uint32_t addr) {
    asm volatile("ldmatrix.sync.aligned.m8n8.x4.shared.b16 {%0,%1,%2,%3}, [%4];"
                 : "=r"(r0), "=r"(r1), "=r"(r2), "=r"(r3) : "r"(addr));
}
__device__ __forceinline__ void mma16816(float* c, const uint32_t* a,
                                         uint32_t b0, uint32_t b1) {
    asm volatile(
        "mma.sync.aligned.m16n8k16.row.col.f32.bf16.bf16.f32 "
        "{%0,%1,%2,%3}, {%4,%5,%6,%7}, {%8,%9}, {%0,%1,%2,%3};"
        : "+f"(c[0]), "+f"(c[1]), "+f"(c[2]), "+f"(c[3])
        : "r"(a[0]), "r"(a[1]), "r"(a[2]), "r"(a[3]), "r"(b0), "r"(b1));
}
__device__ __forceinline__ void split2(float f0, float f1,
                                       uint32_t& hw, uint32_t& lw) {
    __nv_bfloat16 h0 = __float2bfloat16(f0);
    __nv_bfloat16 h1 = __float2bfloat16(f1);
    __nv_bfloat16 l0 = __float2bfloat16(f0 - __bfloat162float(h0));
    __nv_bfloat16 l1 = __float2bfloat16(f1 - __bfloat162float(h1));
    hw = (uint32_t)__bfloat16_as_ushort(h0) |
         ((uint32_t)__bfloat16_as_ushort(h1) << 16);
    lw = (uint32_t)__bfloat16_as_ushort(l0) |
         ((uint32_t)__bfloat16_as_ushort(l1) << 16);
}
__device__ __forceinline__ void cp16(uint32_t dst, const void* src) {
    asm volatile("cp.async.cg.shared.global [%0], [%1], 16;"
                 :: "r"(dst), "l"(src));
}

// ---------------------------------------------------------------------------
// fp32 -> bf16 hi/lo split (flat, vectorized by 4)
// ---------------------------------------------------------------------------
__global__ void cvt_hilo(const float* __restrict__ in,
                         __nv_bfloat16* __restrict__ hi,
                         __nv_bfloat16* __restrict__ lo, int n4)
{
    int i = blockIdx.x * blockDim.x + threadIdx.x;
    if (i >= n4) return;
    float4 v = reinterpret_cast<const float4*>(in)[i];
    uint32_t hw0, lw0, hw1, lw1;
    split2(v.x, v.y, hw0, lw0);
    split2(v.z, v.w, hw1, lw1);
    reinterpret_cast<uint2*>(hi)[i] = make_uint2(hw0, hw1);
    reinterpret_cast<uint2*>(lo)[i] = make_uint2(lw0, lw1);
}

// Merged conversion of the 4 weight matrices (blockIdx.y selects matrix).
__global__ void cvt_hilo_w(
    const float* __restrict__ w0, const float* __restrict__ w1,
    const float* __restrict__ w2, const float* __restrict__ w3,
    __nv_bfloat16* __restrict__ h0p, __nv_bfloat16* __restrict__ l0p,
    __nv_bfloat16* __restrict__ h1p, __nv_bfloat16* __restrict__ l1p,
    __nv_bfloat16* __restrict__ h2p, __nv_bfloat16* __restrict__ l2p,
    __nv_bfloat16* __restrict__ h3p, __nv_bfloat16* __restrict__ l3p)
{
    const int n4 = DD * DD / 4;
    int i = blockIdx.x * blockDim.x + threadIdx.x;
    if (i >= n4) return;
    int z = blockIdx.y;
    const float* in = (z == 0) ? w0 : (z == 1) ? w1 : (z == 2) ? w2 : w3;
    __nv_bfloat16* hi = (z == 0) ? h0p : (z == 1) ? h1p : (z == 2) ? h2p : h3p;
    __nv_bfloat16* lo = (z == 0) ? l0p : (z == 1) ? l1p : (z == 2) ? l2p : l3p;
    float4 v = reinterpret_cast<const float4*>(in)[i];
    uint32_t hw0, lw0, hw1, lw1;
    split2(v.x, v.y, hw0, lw0);
    split2(v.z, v.w, hw1, lw1);
    reinterpret_cast<uint2*>(hi)[i] = make_uint2(hw0, hw1);
    reinterpret_cast<uint2*>(lo)[i] = make_uint2(lw0, lw1);
}

// ---------------------------------------------------------------------------
// fp32 v [B,S,H,HD] -> bf16 hi/lo vt [B,H,HD,S] (transposed, coalesced)
// ---------------------------------------------------------------------------
__global__ __launch_bounds__(256) void cvt_transpose_v(
    const float* __restrict__ src,
    __nv_bfloat16* __restrict__ hi,
    __nv_bfloat16* __restrict__ lo)
{
    __shared__ __nv_bfloat16 th[64][66], tl[64][66];
    const int bh = blockIdx.y;
    const int b  = bh / HH, h = bh % HH;
    const int s0 = blockIdx.x * 64;
    const int tid = threadIdx.x;

#pragma unroll
    for (int it = 0; it < 8; it++) {
        int i = tid + it * 256;
        int d2 = i & 31, sl = i >> 5;
        float2 v = reinterpret_cast<const float2*>(src)
                       [((size_t)(b * SS + s0 + sl) * HH + h) * 32 + d2];
        __nv_bfloat16 h0 = __float2bfloat16(v.x);
        __nv_bfloat16 h1 = __float2bfloat16(v.y);
        th[d2*2  ][sl] = h0;
        th[d2*2+1][sl] = h1;
        tl[d2*2  ][sl] = __float2bfloat16(v.x - __bfloat162float(h0));
        tl[d2*2+1][sl] = __float2bfloat16(v.y - __bfloat162float(h1));
    }
    __syncthreads();
#pragma unroll
    for (int it = 0; it < 8; it++) {
        int i = tid + it * 256;
        int su = i & 31, d = i >> 5;
        uint32_t hw = (uint32_t)__bfloat16_as_ushort(th[d][su*2]) |
                      ((uint32_t)__bfloat16_as_ushort(th[d][su*2+1]) << 16);
        uint32_t lw = (uint32_t)__bfloat16_as_ushort(tl[d][su*2]) |
                      ((uint32_t)__bfloat16_as_ushort(tl[d][su*2+1]) << 16);
        size_t o = ((size_t)(bh * HD + d) * SS + s0) / 2 + su;
        reinterpret_cast<uint32_t*>(hi)[o] = hw;
        reinterpret_cast<uint32_t*>(lo)[o] = lw;
    }
}

// ---------------------------------------------------------------------------
// Shared GEMM mainloop (NT): acc += A[bm:bm+128] x W[bn:bn+128]^T over K=DD.
// cp.async 2-stage pipeline, pre-split bf16 hi/lo, 3-term fp32 accum.
// ---------------------------------------------------------------------------
#define GROW_B   80u
#define GARR_B   10240u
#define GSM_B    (2u*4u*GARR_B)

__device__ __forceinline__ void gemm_core(
    const __nv_bfloat16* __restrict__ Ah, const __nv_bfloat16* __restrict__ Al,
    const __nv_bfloat16* __restrict__ Bh, const __nv_bfloat16* __restrict__ Bl,
    uint32_t sb, int tid, int bm, int bn, float (&acc)[4][4][4])
{
    const int wid  = tid >> 5;
    const int lane = tid & 31;
    const int wm = (wid & 1) * 64;
    const int wn = (wid >> 1) * 32;
    const int lrow = lane & 15;
    const int lcol = (lane >> 4) * 8;

    auto prefetch = [&](int st, int k0) {
#pragma unroll
        for (int p = 0; p < 8; p++) {
            int idx = tid + p * 256;
            int arr = idx >> 9;
            int sub = idx & 511;
            int r   = sub >> 2;
            int c4  = sub & 3;
            size_t off;
            if (arr < 2) off = (size_t)(bm + r) * DD + k0 + c4 * 8;
            else         off = (size_t)(bn + r) * DD + k0 + c4 * 8;
            const __nv_bfloat16* gp =
                (arr == 0 ? Ah : arr == 1 ? Al : arr == 2 ? Bh : Bl) + off;
            uint32_t dst = sb + (uint32_t)(st * 4 + arr) * GARR_B
                         + (uint32_t)r * GROW_B + (uint32_t)c4 * 16u;
            cp16(dst, gp);
        }
    };

    prefetch(0, 0);
    asm volatile("cp.async.commit_group;" ::: "memory");

    int st = 0;
    for (int k0 = 0; k0 < DD; k0 += 32) {
        if (k0 + 32 < DD) {
            prefetch(st ^ 1, k0 + 32);
            asm volatile("cp.async.commit_group;" ::: "memory");
            asm volatile("cp.async.wait_group 1;" ::: "memory");
        } else {
            asm volatile("cp.async.wait_group 0;" ::: "memory");
        }
        __syncthreads();

        const uint32_t bAh = sb + (uint32_t)(st * 4 + 0) * GARR_B;
        const uint32_t bAl = sb + (uint32_t)(st * 4 + 1) * GARR_B;
        const uint32_t bBh = sb + (uint32_t)(st * 4 + 2) * GARR_B;
        const uint32_t bBl = sb + (uint32_t)(st * 4 + 3) * GARR_B;

#pragma unroll
        for (int kk = 0; kk < 32; kk += 16) {
            uint32_t ah[4][4], al[4][4], bh[4][2], bl[4][2];
#pragma unroll
            for (int mt = 0; mt < 4; mt++) {
                uint32_t ra = (uint32_t)(wm + mt*16 + lrow) * GROW_B
                            + (uint32_t)(kk + lcol) * 2u;
                ldm4(ah[mt][0], ah[mt][1], ah[mt][2], ah[mt][3], bAh + ra);
                ldm4(al[mt][0], al[mt][1], al[mt][2], al[mt][3], bAl + ra);
            }
#pragma unroll
            for (int np = 0; np < 2; np++) {
                uint32_t rb = (uint32_t)(wn + np*16 + lrow) * GROW_B
                            + (uint32_t)(kk + lcol) * 2u;
                uint32_t t0, t1, t2, t3;
                ldm4(t0, t1, t2, t3, bBh + rb);
                bh[2*np][0] = t0; bh[2*np][1] = t2;
                bh[2*np+1][0] = t1; bh[2*np+1][1] = t3;
                ldm4(t0, t1, t2, t3, bBl + rb);
                bl[2*np][0] = t0; bl[2*np][1] = t2;
                bl[2*np+1][0] = t1; bl[2*np+1][1] = t3;
            }
#pragma unroll
            for (int mt = 0; mt < 4; mt++)
#pragma unroll
                for (int nt = 0; nt < 4; nt++) {
                    mma16816(acc[mt][nt], ah[mt], bh[nt][0], bh[nt][1]);
                    mma16816(acc[mt][nt], ah[mt], bl[nt][0], bl[nt][1]);
                    mma16816(acc[mt][nt], al[mt], bh[nt][0], bh[nt][1]);
                }
        }
        __syncthreads();
        st ^= 1;
    }
}

// ---------------------------------------------------------------------------
// Fused QKV projection: blockIdx.z selects {Q, K, V}.
// Q/K: rope + scale + hi/lo split -> [B,H,S,HD].  V: fp32 [B,S,H,HD].
// Q scale folds log2(e) so attention softmax can use exp2.
// Occupancy: (256, 2) caps regs at 128 -> 2 CTAs/SM (16 warps).
// ---------------------------------------------------------------------------
#define QSCALE 0.1803368801111355f   // (1/8) * log2(e)

__global__ __launch_bounds__(256, 2) void gemm_qkv(
    const __nv_bfloat16* __restrict__ Xh, const __nv_bfloat16* __restrict__ Xl,
    const __nv_bfloat16* __restrict__ Wqh, const __nv_bfloat16* __restrict__ Wql,
    const __nv_bfloat16* __restrict__ Wkh, const __nv_bfloat16* __restrict__ Wkl,
    const __nv_bfloat16* __restrict__ Wvh, const __nv_bfloat16* __restrict__ Wvl,
    __nv_bfloat16* __restrict__ Qh, __nv_bfloat16* __restrict__ Ql,
    __nv_bfloat16* __restrict__ Kh, __nv_bfloat16* __restrict__ Kl,
    float* __restrict__ V,
    const float* __restrict__ fc, const float* __restrict__ fs)
{
    extern __shared__ char gsm[];
    const uint32_t sb = smem_u32(gsm);
    const int tid = threadIdx.x;
    const int bm = blockIdx.y * 128;
    const int bn = blockIdx.x * 128;
    const int z  = blockIdx.z;

    const __nv_bfloat16* Bh = (z == 0) ? Wqh : (z == 1) ? Wkh : Wvh;
    const __nv_bfloat16* Bl = (z == 0) ? Wql : (z == 1) ? Wkl : Wvl;

    float acc[4][4][4];
#pragma unroll
    for (int i = 0; i < 4; i++)
#pragma unroll
        for (int j = 0; j < 4; j++)
#pragma unroll
            for (int r = 0; r < 4; r++) acc[i][j][r] = 0.f;

    gemm_core(Xh, Xl, Bh, Bl, sb, tid, bm, bn, acc);

    const int lane = tid & 31;
    const int wid  = tid >> 5;
    const int wm = (wid & 1) * 64;
    const int wn = (wid >> 1) * 32;
    const int g  = lane >> 2;
    const int t2 = (lane & 3) * 2;

    if (z == 2) {
#pragma unroll
        for (int mt = 0; mt < 4; mt++)
#pragma unroll
            for (int nt = 0; nt < 4; nt++) {
                int r0 = bm + wm + mt*16 + g;
                int cc = bn + wn + nt*8 + t2;
                *reinterpret_cast<float2*>(&V[(size_t)r0 * DD + cc]) =
                    make_float2(acc[mt][nt][0], acc[mt][nt][1]);
                *reinterpret_cast<float2*>(&V[(size_t)(r0 + 8) * DD + cc]) =
                    make_float2(acc[mt][nt][2], acc[mt][nt][3]);
            }
    } else {
        const float scale = (z == 0) ? QSCALE : 1.0f;
        uint32_t* oh = reinterpret_cast<uint32_t*>(z == 0 ? Qh : Kh);
        uint32_t* ol = reinterpret_cast<uint32_t*>(z == 0 ? Ql : Kl);
#pragma unroll
        for (int mt = 0; mt < 4; mt++)
#pragma unroll
            for (int nt = 0; nt < 4; nt++) {
                int cc  = bn + wn + nt*8 + t2;
                int h   = cc >> 6;
                int hd2 = (cc & 63) >> 1;
#pragma unroll
                for (int rr = 0; rr < 2; rr++) {
                    int row = bm + wm + mt*16 + g + rr*8;
                    int s = row & (SS - 1);
                    int b = row >> 11;
                    float c  = fc[s * 32 + hd2];
                    float sn = fs[s * 32 + hd2];
                    float a0 = acc[mt][nt][rr*2 + 0];
                    float a1 = acc[mt][nt][rr*2 + 1];
                    float r0v = (a0 * c - a1 * sn) * scale;
                    float r1v = (a0 * sn + a1 * c) * scale;
                    uint32_t hw, lw;
                    split2(r0v, r1v, hw, lw);
                    size_t o = ((size_t)(b * HH + h) * SS + s) * 32 + hd2;
                    oh[o] = hw;
                    ol[o] = lw;
                }
            }
    }
}

// ---------------------------------------------------------------------------
// Output projection GEMM: C fp32 = AO * WO^T.  (256, 2) occupancy cap.
// ---------------------------------------------------------------------------
__global__ __launch_bounds__(256, 2) void gemm_hmma(
    const __nv_bfloat16* __restrict__ Ah, const __nv_bfloat16* __restrict__ Al,
    const __nv_bfloat16* __restrict__ Bh, const __nv_bfloat16* __restrict__ Bl,
    float* __restrict__ C)
{
    extern __shared__ char gsm[];
    const uint32_t sb = smem_u32(gsm);
    const int tid = threadIdx.x;
    const int bm = blockIdx.y * 128;
    const int bn = blockIdx.x * 128;

    float acc[4][4][4];
#pragma unroll
    for (int i = 0; i < 4; i++)
#pragma unroll
        for (int j = 0; j < 4; j++)
#pragma unroll
            for (int r = 0; r < 4; r++) acc[i][j][r] = 0.f;

    gemm_core(Ah, Al, Bh, Bl, sb, tid, bm, bn, acc);

    const int lane = tid & 31;
    const int wid  = tid >> 5;
    const int wm = (wid & 1) * 64;
    const int wn = (wid >> 1) * 32;
    const int g  = lane >> 2;
    const int t2 = (lane & 3) * 2;
#pragma unroll
    for (int mt = 0; mt < 4; mt++)
#pragma unroll
        for (int nt = 0; nt < 4; nt++) {
            int r0 = bm + wm + mt*16 + g;
            int cc = bn + wn + nt*8 + t2;
            *reinterpret_cast<float2*>(&C[(size_t)r0 * DD + cc]) =
                make_float2(acc[mt][nt][0], acc[mt][nt][1]);
            *reinterpret_cast<float2*>(&C[(size_t)(r0 + 8) * DD + cc]) =
                make_float2(acc[mt][nt][2], acc[mt][nt][3]);
        }
}

// ---------------------------------------------------------------------------
// HMMA causal flash attention (64q/128-thread body, (128,3) occupancy).
// Scores pre-scaled by log2(e) -> exp2f softmax.
// Output written as bf16 hi/lo split directly (aoh/aol, [B,S,D]).
// ---------------------------------------------------------------------------
__global__ __launch_bounds__(128, 3) void attn_hmma(
    const __nv_bfloat16* __restrict__ Qh, const __nv_bfloat16* __restrict__ Ql,
    const __nv_bfloat16* __restrict__ Kh, const __nv_bfloat16* __restrict__ Kl,
    const __nv_bfloat16* __restrict__ Vth, const __nv_bfloat16* __restrict__ Vtl,
    __nv_bfloat16* __restrict__ AOh, __nv_bfloat16* __restrict__ AOl)
{
    __shared__ __align__(16) __nv_bfloat16 sA[64][72], sB[64][72];
    __shared__ __align__(16) __nv_bfloat16 sC[64][72], sD[64][72];

    const int bh = blockIdx.y;
    const int b  = bh / HH, h = bh % HH;
    const int qt = gridDim.x - 1 - blockIdx.x;
    const int q0 = qt * 64;
    const int tid  = threadIdx.x;
    const int wid  = tid >> 5;
    const int lane = tid & 31;
    const int lrow = lane & 15;
    const int lcol = (lane >> 4) * 8;
    const int g  = lane >> 2;
    const int tq = lane & 3;

    const uint4* gqh = reinterpret_cast<const uint4*>(Qh);
    const uint4* gql = reinterpret_cast<const uint4*>(Ql);
    const uint4* gkh = reinterpret_cast<const uint4*>(Kh);
    const uint4* gkl = reinterpret_cast<const uint4*>(Kl);
    const uint4* gvh = reinterpret_cast<const uint4*>(Vth);
    const uint4* gvl = reinterpret_cast<const uint4*>(Vtl);

#pragma unroll
    for (int it = 0; it < 8; it++) {
        int idx = tid + it * 128;
        int arr = idx >> 9;
        int r = (idx >> 3) & 63;
        int c = idx & 7;
        uint4 val = (arr ? gql : gqh)[((size_t)bh * SS + q0 + r) * 8 + c];
        reinterpret_cast<uint4*>(arr ? &sB[0][0] : &sA[0][0])[r * 9 + c] = val;
    }
    __syncthreads();

    uint32_t qfh[4][4], qfl[4][4];
#pragma unroll
    for (int kk = 0; kk < 4; kk++) {
        ldm4(qfh[kk][0], qfh[kk][1], qfh[kk][2], qfh[kk][3],
             smem_u32(&sA[wid*16 + lrow][kk*16 + lcol]));
        ldm4(qfl[kk][0], qfl[kk][1], qfl[kk][2], qfl[kk][3],
             smem_u32(&sB[wid*16 + lrow][kk*16 + lcol]));
    }

    float ov[8][4];
#pragma unroll
    for (int nt = 0; nt < 8; nt++)
#pragma unroll
        for (int r = 0; r < 4; r++) ov[nt][r] = 0.f;
    float m0 = -1e30f, m1 = -1e30f, l0 = 0.f, l1 = 0.f;

    for (int k0 = 0; k0 <= q0; k0 += 64) {
        __syncthreads();
#pragma unroll
        for (int it = 0; it < 16; it++) {
            int idx = tid + it * 128;
            int arr = idx >> 9;
            int r = (idx >> 3) & 63;
            int c = idx & 7;
            uint4 val;
            if      (arr == 0) val = gkh[((size_t)bh * SS + k0 + r) * 8 + c];
            else if (arr == 1) val = gkl[((size_t)bh * SS + k0 + r) * 8 + c];
            else if (arr == 2) val = gvh[((size_t)bh * HD + r) * (SS/8) + k0/8 + c];
            else               val = gvl[((size_t)bh * HD + r) * (SS/8) + k0/8 + c];
            __nv_bfloat16* dst = (arr == 0) ? &sA[0][0] : (arr == 1) ? &sB[0][0]
                               : (arr == 2) ? &sC[0][0] : &sD[0][0];
            reinterpret_cast<uint4*>(dst)[r * 9 + c] = val;
        }
        __syncthreads();

        float sc[8][4];
#pragma unroll
        for (int nt = 0; nt < 8; nt++)
#pragma unroll
            for (int r = 0; r < 4; r++) sc[nt][r] = 0.f;

#pragma unroll
        for (int kk = 0; kk < 4; kk++) {
            uint32_t kfh[8][2], kfl[8][2];
#pragma unroll
            for (int np = 0; np < 4; np++) {
                uint32_t t0, t1, t2, t3;
                ldm4(t0, t1, t2, t3, smem_u32(&sA[np*16 + lrow][kk*16 + lcol]));
                kfh[2*np][0] = t0; kfh[2*np][1] = t2;
                kfh[2*np+1][0] = t1; kfh[2*np+1][1] = t3;
                ldm4(t0, t1, t2, t3, smem_u32(&sB[np*16 + lrow][kk*16 + lcol]));
                kfl[2*np][0] = t0; kfl[2*np][1] = t2;
                kfl[2*np+1][0] = t1; kfl[2*np+1][1] = t3;
            }
#pragma unroll
            for (int nt = 0; nt < 8; nt++) {
                mma16816(sc[nt], qfh[kk], kfh[nt][0], kfh[nt][1]);
                mma16816(sc[nt], qfh[kk], kfl[nt][0], kfl[nt][1]);
                mma16816(sc[nt], qfl[kk], kfh[nt][0], kfh[nt][1]);
            }
        }

        if (k0 == q0) {
            const int r0 = wid*16 + g, r1 = r0 + 8;
#pragma unroll
            for (int nt = 0; nt < 8; nt++) {
                int key0 = nt*8 + tq*2, key1 = key0 + 1;
                if (key0 > r0) sc[nt][0] = -1e30f;
                if (key1 > r0) sc[nt][1] = -1e30f;
                if (key0 > r1) sc[nt][2] = -1e30f;
                if (key1 > r1) sc[nt][3] = -1e30f;
            }
        }

        float rm0 = -1e30f, rm1 = -1e30f;
#pragma unroll
        for (int nt = 0; nt < 8; nt++) {
            rm0 = fmaxf(rm0, fmaxf(sc[nt][0], sc[nt][1]));
            rm1 = fmaxf(rm1, fmaxf(sc[nt][2], sc[nt][3]));
        }
        rm0 = fmaxf(rm0, __shfl_xor_sync(0xffffffffu, rm0, 1));
        rm0 = fmaxf(rm0, __shfl_xor_sync(0xffffffffu, rm0, 2));
        rm1 = fmaxf(rm1, __shfl_xor_sync(0xffffffffu, rm1, 1));
        rm1 = fmaxf(rm1, __shfl_xor_sync(0xffffffffu, rm1, 2));
        float mn0 = fmaxf(m0, rm0), mn1 = fmaxf(m1, rm1);
        float corr0 = exp2f(m0 - mn0), corr1 = exp2f(m1 - mn1);
        m0 = mn0; m1 = mn1;

        float ps0 = 0.f, ps1 = 0.f;
#pragma unroll
        for (int nt = 0; nt < 8; nt++) {
            sc[nt][0] = exp2f(sc[nt][0] - m0); ps0 += sc[nt][0];
            sc[nt][1] = exp2f(sc[nt][1] - m0); ps0 += sc[nt][1];
            sc[nt][2] = exp2f(sc[nt][2] - m1); ps1 += sc[nt][2];
            sc[nt][3] = exp2f(sc[nt][3] - m1); ps1 += sc[nt][3];
        }
        l0 = l0 * corr0 + ps0;
        l1 = l1 * corr1 + ps1;
#pragma unroll
        for (int nt = 0; nt < 8; nt++) {
            ov[nt][0] *= corr0; ov[nt][1] *= corr0;
            ov[nt][2] *= corr1; ov[nt][3] *= corr1;
        }

        // PV: P packed per-kk (shrinks live register set)
#pragma unroll
        for (int kk = 0; kk < 4; kk++) {
            uint32_t pfh[4], pfl[4];
            split2(sc[2*kk  ][0], sc[2*kk  ][1], pfh[0], pfl[0]);
            split2(sc[2*kk  ][2], sc[2*kk  ][3], pfh[1], pfl[1]);
            split2(sc[2*kk+1][0], sc[2*kk+1][1], pfh[2], pfl[2]);
            split2(sc[2*kk+1][2], sc[2*kk+1][3], pfh[3], pfl[3]);

            uint32_t vfh[8][2], vfl[8][2];
#pragma unroll
            for (int np = 0; np < 4; np++) {
                uint32_t t0, t1, t2, t3;
                ldm4(t0, t1, t2, t3, smem_u32(&sC[np*16 + lrow][kk*16 + lcol]));
                vfh[2*np][0] = t0; vfh[2*np][1] = t2;
                vfh[2*np+1][0] = t1; vfh[2*np+1][1] = t3;
                ldm4(t0, t1, t2, t3, smem_u32(&sD[np*16 + lrow][kk*16 + lcol]));
                vfl[2*np][0] = t0; vfl[2*np][1] = t2;
                vfl[2*np+1][0] = t1; vfl[2*np+1][1] = t3;
            }
#pragma unroll
            for (int nt = 0; nt < 8; nt++) {
                mma16816(ov[nt], pfh, vfh[nt][0], vfh[nt][1]);
                mma16816(ov[nt], pfh, vfl[nt][0], vfl[nt][1]);
                mma16816(ov[nt], pfl, vfh[nt][0], vfh[nt][1]);
            }
        }
    }

    l0 += __shfl_xor_sync(0xffffffffu, l0, 1);
    l0 += __shfl_xor_sync(0xffffffffu, l0, 2);
    l1 += __shfl_xor_sync(0xffffffffu, l1, 1);
    l1 += __shfl_xor_sync(0xffffffffu, l1, 2);
    float inv0 = 1.f / l0, inv1 = 1.f / l1;

    uint32_t* aoh = reinterpret_cast<uint32_t*>(AOh);
    uint32_t* aol = reinterpret_cast<uint32_t*>(AOl);
    const int r0 = q0 + wid*16 + g;
    const int r1 = r0 + 8;
#pragma unroll
    for (int nt = 0; nt < 8; nt++) {
        int col = nt*8 + tq*2;
        uint32_t hw, lw;
        split2(ov[nt][0] * inv0, ov[nt][1] * inv0, hw, lw);
        size_t o0 = (((size_t)(b * SS + r0) * DD) + h * HD + col) >> 1;
        aoh[o0] = hw; aol[o0] = lw;
        split2(ov[nt][2] * inv1, ov[nt][3] * inv1, hw, lw);
        size_t o1 = (((size_t)(b * SS + r1) * DD) + h * HD + col) >> 1;
        aoh[o1] = hw; aol[o1] = lw;
    }
}

// ---------------------------------------------------------------------------
// Launch
// ---------------------------------------------------------------------------
extern "C" void kernel_launch(void* const* d_in, const int* in_sizes, int n_in,
                              void* d_out, int out_size)
{
    const float* x  = (const float*)d_in[0];
    const float* wq = (const float*)d_in[1];
    const float* wk = (const float*)d_in[2];
    const float* wv = (const float*)d_in[3];
    const float* wo = (const float*)d_in[4];
    const float* fc = (const float*)d_in[5];
    const float* fs = (const float*)d_in[6];
    float* out = (float*)d_out;

    float* v;
    cudaGetSymbolAddress((void**)&v, g_v);

    __nv_bfloat16 *xh, *xl, *aoh, *aol;
    __nv_bfloat16 *wqh, *wql, *wkh, *wkl, *wvh, *wvl, *woh, *wol;
    __nv_bfloat16 *qh, *ql, *kh, *kl, *vth, *vtl;
    cudaGetSymbolAddress((void**)&xh,  g_xh);  cudaGetSymbolAddress((void**)&xl,  g_xl);
    cudaGetSymbolAddress((void**)&aoh, g_aoh); cudaGetSymbolAddress((void**)&aol, g_aol);
    cudaGetSymbolAddress((void**)&wqh, g_wqh); cudaGetSymbolAddress((void**)&wql, g_wql);
    cudaGetSymbolAddress((void**)&wkh, g_wkh); cudaGetSymbolAddress((void**)&wkl, g_wkl);
    cudaGetSymbolAddress((void**)&wvh, g_wvh); cudaGetSymbolAddress((void**)&wvl, g_wvl);
    cudaGetSymbolAddress((void**)&woh, g_woh); cudaGetSymbolAddress((void**)&wol, g_wol);
    cudaGetSymbolAddress((void**)&qh,  g_qh);  cudaGetSymbolAddress((void**)&ql,  g_ql);
    cudaGetSymbolAddress((void**)&kh,  g_kh);  cudaGetSymbolAddress((void**)&kl,  g_kl);
    cudaGetSymbolAddress((void**)&vth, g_vth); cudaGetSymbolAddress((void**)&vtl, g_vtl);

    cudaFuncSetAttribute(gemm_qkv,
                         cudaFuncAttributeMaxDynamicSharedMemorySize, GSM_B);
    cudaFuncSetAttribute(gemm_hmma,
                         cudaFuncAttributeMaxDynamicSharedMemorySize, GSM_B);

    const int NX4 = MM * DD / 4;
    const int NW4 = DD * DD / 4;
    cvt_hilo<<<(NX4 + 255)/256, 256>>>(x, xh, xl, NX4);
    dim3 gw((NW4 + 255)/256, 4);
    cvt_hilo_w<<<gw, 256>>>(wq, wk, wv, wo,
                            wqh, wql, wkh, wkl, wvh, wvl, woh, wol);

    dim3 gq(DD / 128, MM / 128, 3);
    gemm_qkv<<<gq, 256, GSM_B>>>(xh, xl, wqh, wql, wkh, wkl, wvh, wvl,
                                 qh, ql, kh, kl, v, fc, fs);

    dim3 gt(SS / 64, BB * HH);
    cvt_transpose_v<<<gt, 256>>>(v, vth, vtl);

    dim3 ga(SS / 64, BB * HH);
    attn_hmma<<<ga, 128>>>(qh, ql, kh, kl, vth, vtl, aoh, aol);

    dim3 gg(DD / 128, MM / 128);
    gemm_hmma<<<gg, 256, GSM_B>>>(aoh, aol, woh, wol, out);
}

// round 16
// speedup vs baseline: 1.0127x; 1.0127x over previous
#include <cuda_runtime.h>
#include <cuda_bf16.h>
#include <cstdint>
#include <cstddef>

// Problem constants
#define BB   2
#define SS   2048
#define DD   1024
#define HH   16
#define HD   64
#define MM   (BB*SS)

// fp32 scratch for V
__device__ float g_v [BB*SS*DD];

// bf16 hi/lo split scratch
__device__ __nv_bfloat16 g_xh [MM*DD], g_xl [MM*DD];
__device__ __nv_bfloat16 g_aoh[MM*DD], g_aol[MM*DD];
__device__ __nv_bfloat16 g_wqh[DD*DD], g_wql[DD*DD];
__device__ __nv_bfloat16 g_wkh[DD*DD], g_wkl[DD*DD];
__device__ __nv_bfloat16 g_wvh[DD*DD], g_wvl[DD*DD];
__device__ __nv_bfloat16 g_woh[DD*DD], g_wol[DD*DD];

// attention operands: q,k [B,H,S,HD]; v transposed [B,H,HD,S]
__device__ __nv_bfloat16 g_qh [MM*DD], g_ql [MM*DD];
__device__ __nv_bfloat16 g_kh [MM*DD], g_kl [MM*DD];
__device__ __nv_bfloat16 g_vth[MM*DD], g_vtl[MM*DD];

// ---------------------------------------------------------------------------
// helpers
// ---------------------------------------------------------------------------
__device__ __forceinline__ uint32_t smem_u32(const void* p) {
    uint32_t a;
    asm("{ .reg .u64 t; cvta.to.shared.u64 t, %1; cvt.u32.u64 %0, t; }"
        : "=r"(a) : "l"(p));
    return a;
}
__device__ __forceinline__ void ldm4(uint32_t& r0, uint32_t& r1, uint32_t& r2,
                                     uint32_t& r3, uint32_t addr) {
    asm volatile("ldmatrix.sync.aligned.m8n8.x4.shared.b16 {%0,%1,%2,%3}, [%4];"
                 : "=r"(r0), "=r"(r1), "=r"(r2), "=r"(r3) : "r"(addr));
}
__device__ __forceinline__ void mma16816(float* c, const uint32_t* a,
                                         uint32_t b0, uint32_t b1) {
    asm volatile(
        "mma.sync.aligned.m16n8k16.row.col.f32.bf16.bf16.f32 "
        "{%0,%1,%2,%3}, {%4,%5,%6,%7}, {%8,%9}, {%0,%1,%2,%3};"
        : "+f"(c[0]), "+f"(c[1]), "+f"(c[2]), "+f"(c[3])
        : "r"(a[0]), "r"(a[1]), "r"(a[2]), "r"(a[3]), "r"(b0), "r"(b1));
}
__device__ __forceinline__ void split2(float f0, float f1,
                                       uint32_t& hw, uint32_t& lw) {
    __nv_bfloat16 h0 = __float2bfloat16(f0);
    __nv_bfloat16 h1 = __float2bfloat16(f1);
    __nv_bfloat16 l0 = __float2bfloat16(f0 - __bfloat162float(h0));
    __nv_bfloat16 l1 = __float2bfloat16(f1 - __bfloat162float(h1));
    hw = (uint32_t)__bfloat16_as_ushort(h0) |
         ((uint32_t)__bfloat16_as_ushort(h1) << 16);
    lw = (uint32_t)__bfloat16_as_ushort(l0) |
         ((uint32_t)__bfloat16_as_ushort(l1) << 16);
}
__device__ __forceinline__ void cp16(uint32_t dst, const void* src) {
    asm volatile("cp.async.cg.shared.global [%0], [%1], 16;"
                 :: "r"(dst), "l"(src));
}

// ---------------------------------------------------------------------------
// fp32 -> bf16 hi/lo split (flat, vectorized by 4)
// ---------------------------------------------------------------------------
__global__ void cvt_hilo(const float* __restrict__ in,
                         __nv_bfloat16* __restrict__ hi,
                         __nv_bfloat16* __restrict__ lo, int n4)
{
    int i = blockIdx.x * blockDim.x + threadIdx.x;
    if (i >= n4) return;
    float4 v = reinterpret_cast<const float4*>(in)[i];
    uint32_t hw0, lw0, hw1, lw1;
    split2(v.x, v.y, hw0, lw0);
    split2(v.z, v.w, hw1, lw1);
    reinterpret_cast<uint2*>(hi)[i] = make_uint2(hw0, hw1);
    reinterpret_cast<uint2*>(lo)[i] = make_uint2(lw0, lw1);
}

// Merged conversion of the 4 weight matrices (blockIdx.y selects matrix).
__global__ void cvt_hilo_w(
    const float* __restrict__ w0, const float* __restrict__ w1,
    const float* __restrict__ w2, const float* __restrict__ w3,
    __nv_bfloat16* __restrict__ h0p, __nv_bfloat16* __restrict__ l0p,
    __nv_bfloat16* __restrict__ h1p, __nv_bfloat16* __restrict__ l1p,
    __nv_bfloat16* __restrict__ h2p, __nv_bfloat16* __restrict__ l2p,
    __nv_bfloat16* __restrict__ h3p, __nv_bfloat16* __restrict__ l3p)
{
    const int n4 = DD * DD / 4;
    int i = blockIdx.x * blockDim.x + threadIdx.x;
    if (i >= n4) return;
    int z = blockIdx.y;
    const float* in = (z == 0) ? w0 : (z == 1) ? w1 : (z == 2) ? w2 : w3;
    __nv_bfloat16* hi = (z == 0) ? h0p : (z == 1) ? h1p : (z == 2) ? h2p : h3p;
    __nv_bfloat16* lo = (z == 0) ? l0p : (z == 1) ? l1p : (z == 2) ? l2p : l3p;
    float4 v = reinterpret_cast<const float4*>(in)[i];
    uint32_t hw0, lw0, hw1, lw1;
    split2(v.x, v.y, hw0, lw0);
    split2(v.z, v.w, hw1, lw1);
    reinterpret_cast<uint2*>(hi)[i] = make_uint2(hw0, hw1);
    reinterpret_cast<uint2*>(lo)[i] = make_uint2(lw0, lw1);
}

// ---------------------------------------------------------------------------
// fp32 v [B,S,H,HD] -> bf16 hi/lo vt [B,H,HD,S] (transposed, coalesced)
// ---------------------------------------------------------------------------
__global__ __launch_bounds__(256) void cvt_transpose_v(
    const float* __restrict__ src,
    __nv_bfloat16* __restrict__ hi,
    __nv_bfloat16* __restrict__ lo)
{
    __shared__ __nv_bfloat16 th[64][66], tl[64][66];
    const int bh = blockIdx.y;
    const int b  = bh / HH, h = bh % HH;
    const int s0 = blockIdx.x * 64;
    const int tid = threadIdx.x;

#pragma unroll
    for (int it = 0; it < 8; it++) {
        int i = tid + it * 256;
        int d2 = i & 31, sl = i >> 5;
        float2 v = reinterpret_cast<const float2*>(src)
                       [((size_t)(b * SS + s0 + sl) * HH + h) * 32 + d2];
        __nv_bfloat16 h0 = __float2bfloat16(v.x);
        __nv_bfloat16 h1 = __float2bfloat16(v.y);
        th[d2*2  ][sl] = h0;
        th[d2*2+1][sl] = h1;
        tl[d2*2  ][sl] = __float2bfloat16(v.x - __bfloat162float(h0));
        tl[d2*2+1][sl] = __float2bfloat16(v.y - __bfloat162float(h1));
    }
    __syncthreads();
#pragma unroll
    for (int it = 0; it < 8; it++) {
        int i = tid + it * 256;
        int su = i & 31, d = i >> 5;
        uint32_t hw = (uint32_t)__bfloat16_as_ushort(th[d][su*2]) |
                      ((uint32_t)__bfloat16_as_ushort(th[d][su*2+1]) << 16);
        uint32_t lw = (uint32_t)__bfloat16_as_ushort(tl[d][su*2]) |
                      ((uint32_t)__bfloat16_as_ushort(tl[d][su*2+1]) << 16);
        size_t o = ((size_t)(bh * HD + d) * SS + s0) / 2 + su;
        reinterpret_cast<uint32_t*>(hi)[o] = hw;
        reinterpret_cast<uint32_t*>(lo)[o] = lw;
    }
}

// ---------------------------------------------------------------------------
// Shared GEMM mainloop (NT): acc += A[bm:bm+128] x W[bn:bn+128]^T over K=DD.
// cp.async 2-stage pipeline, pre-split bf16 hi/lo, 3-term fp32 accum.
// ---------------------------------------------------------------------------
#define GROW_B   80u
#define GARR_B   10240u
#define GSM_B    (2u*4u*GARR_B)

__device__ __forceinline__ void gemm_core(
    const __nv_bfloat16* __restrict__ Ah, const __nv_bfloat16* __restrict__ Al,
    const __nv_bfloat16* __restrict__ Bh, const __nv_bfloat16* __restrict__ Bl,
    uint32_t sb, int tid, int bm, int bn, float (&acc)[4][4][4])
{
    const int wid  = tid >> 5;
    const int lane = tid & 31;
    const int wm = (wid & 1) * 64;
    const int wn = (wid >> 1) * 32;
    const int lrow = lane & 15;
    const int lcol = (lane >> 4) * 8;

    auto prefetch = [&](int st, int k0) {
#pragma unroll
        for (int p = 0; p < 8; p++) {
            int idx = tid + p * 256;
            int arr = idx >> 9;
            int sub = idx & 511;
            int r   = sub >> 2;
            int c4  = sub & 3;
            size_t off;
            if (arr < 2) off = (size_t)(bm + r) * DD + k0 + c4 * 8;
            else         off = (size_t)(bn + r) * DD + k0 + c4 * 8;
            const __nv_bfloat16* gp =
                (arr == 0 ? Ah : arr == 1 ? Al : arr == 2 ? Bh : Bl) + off;
            uint32_t dst = sb + (uint32_t)(st * 4 + arr) * GARR_B
                         + (uint32_t)r * GROW_B + (uint32_t)c4 * 16u;
            cp16(dst, gp);
        }
    };

    prefetch(0, 0);
    asm volatile("cp.async.commit_group;" ::: "memory");

    int st = 0;
    for (int k0 = 0; k0 < DD; k0 += 32) {
        if (k0 + 32 < DD) {
            prefetch(st ^ 1, k0 + 32);
            asm volatile("cp.async.commit_group;" ::: "memory");
            asm volatile("cp.async.wait_group 1;" ::: "memory");
        } else {
            asm volatile("cp.async.wait_group 0;" ::: "memory");
        }
        __syncthreads();

        const uint32_t bAh = sb + (uint32_t)(st * 4 + 0) * GARR_B;
        const uint32_t bAl = sb + (uint32_t)(st * 4 + 1) * GARR_B;
        const uint32_t bBh = sb + (uint32_t)(st * 4 + 2) * GARR_B;
        const uint32_t bBl = sb + (uint32_t)(st * 4 + 3) * GARR_B;

#pragma unroll
        for (int kk = 0; kk < 32; kk += 16) {
            uint32_t ah[4][4], al[4][4], bh[4][2], bl[4][2];
#pragma unroll
            for (int mt = 0; mt < 4; mt++) {
                uint32_t ra = (uint32_t)(wm + mt*16 + lrow) * GROW_B
                            + (uint32_t)(kk + lcol) * 2u;
                ldm4(ah[mt][0], ah[mt][1], ah[mt][2], ah[mt][3], bAh + ra);
                ldm4(al[mt][0], al[mt][1], al[mt][2], al[mt][3], bAl + ra);
            }
#pragma unroll
            for (int np = 0; np < 2; np++) {
                uint32_t rb = (uint32_t)(wn + np*16 + lrow) * GROW_B
                            + (uint32_t)(kk + lcol) * 2u;
                uint32_t t0, t1, t2, t3;
                ldm4(t0, t1, t2, t3, bBh + rb);
                bh[2*np][0] = t0; bh[2*np][1] = t2;
                bh[2*np+1][0] = t1; bh[2*np+1][1] = t3;
                ldm4(t0, t1, t2, t3, bBl + rb);
                bl[2*np][0] = t0; bl[2*np][1] = t2;
                bl[2*np+1][0] = t1; bl[2*np+1][1] = t3;
            }
#pragma unroll
            for (int mt = 0; mt < 4; mt++)
#pragma unroll
                for (int nt = 0; nt < 4; nt++) {
                    mma16816(acc[mt][nt], ah[mt], bh[nt][0], bh[nt][1]);
                    mma16816(acc[mt][nt], ah[mt], bl[nt][0], bl[nt][1]);
                    mma16816(acc[mt][nt], al[mt], bh[nt][0], bh[nt][1]);
                }
        }
        __syncthreads();
        st ^= 1;
    }
}

// ---------------------------------------------------------------------------
// Fused QKV projection: blockIdx.z selects {Q, K, V}.
// Q/K: rope + scale + hi/lo split -> [B,H,S,HD].  V: fp32 [B,S,H,HD].
// ---------------------------------------------------------------------------
#define QSCALE 0.1803368801111355f   // (1/8) * log2(e)

__global__ __launch_bounds__(256) void gemm_qkv(
    const __nv_bfloat16* __restrict__ Xh, const __nv_bfloat16* __restrict__ Xl,
    const __nv_bfloat16* __restrict__ Wqh, const __nv_bfloat16* __restrict__ Wql,
    const __nv_bfloat16* __restrict__ Wkh, const __nv_bfloat16* __restrict__ Wkl,
    const __nv_bfloat16* __restrict__ Wvh, const __nv_bfloat16* __restrict__ Wvl,
    __nv_bfloat16* __restrict__ Qh, __nv_bfloat16* __restrict__ Ql,
    __nv_bfloat16* __restrict__ Kh, __nv_bfloat16* __restrict__ Kl,
    float* __restrict__ V,
    const float* __restrict__ fc, const float* __restrict__ fs)
{
    extern __shared__ char gsm[];
    const uint32_t sb = smem_u32(gsm);
    const int tid = threadIdx.x;
    const int bm = blockIdx.y * 128;
    const int bn = blockIdx.x * 128;
    const int z  = blockIdx.z;

    const __nv_bfloat16* Bh = (z == 0) ? Wqh : (z == 1) ? Wkh : Wvh;
    const __nv_bfloat16* Bl = (z == 0) ? Wql : (z == 1) ? Wkl : Wvl;

    float acc[4][4][4];
#pragma unroll
    for (int i = 0; i < 4; i++)
#pragma unroll
        for (int j = 0; j < 4; j++)
#pragma unroll
            for (int r = 0; r < 4; r++) acc[i][j][r] = 0.f;

    gemm_core(Xh, Xl, Bh, Bl, sb, tid, bm, bn, acc);

    const int lane = tid & 31;
    const int wid  = tid >> 5;
    const int wm = (wid & 1) * 64;
    const int wn = (wid >> 1) * 32;
    const int g  = lane >> 2;
    const int t2 = (lane & 3) * 2;

    if (z == 2) {
#pragma unroll
        for (int mt = 0; mt < 4; mt++)
#pragma unroll
            for (int nt = 0; nt < 4; nt++) {
                int r0 = bm + wm + mt*16 + g;
                int cc = bn + wn + nt*8 + t2;
                *reinterpret_cast<float2*>(&V[(size_t)r0 * DD + cc]) =
                    make_float2(acc[mt][nt][0], acc[mt][nt][1]);
                *reinterpret_cast<float2*>(&V[(size_t)(r0 + 8) * DD + cc]) =
                    make_float2(acc[mt][nt][2], acc[mt][nt][3]);
            }
    } else {
        const float scale = (z == 0) ? QSCALE : 1.0f;
        uint32_t* oh = reinterpret_cast<uint32_t*>(z == 0 ? Qh : Kh);
        uint32_t* ol = reinterpret_cast<uint32_t*>(z == 0 ? Ql : Kl);
#pragma unroll
        for (int mt = 0; mt < 4; mt++)
#pragma unroll
            for (int nt = 0; nt < 4; nt++) {
                int cc  = bn + wn + nt*8 + t2;
                int h   = cc >> 6;
                int hd2 = (cc & 63) >> 1;
#pragma unroll
                for (int rr = 0; rr < 2; rr++) {
                    int row = bm + wm + mt*16 + g + rr*8;
                    int s = row & (SS - 1);
                    int b = row >> 11;
                    float c  = fc[s * 32 + hd2];
                    float sn = fs[s * 32 + hd2];
                    float a0 = acc[mt][nt][rr*2 + 0];
                    float a1 = acc[mt][nt][rr*2 + 1];
                    float r0v = (a0 * c - a1 * sn) * scale;
                    float r1v = (a0 * sn + a1 * c) * scale;
                    uint32_t hw, lw;
                    split2(r0v, r1v, hw, lw);
                    size_t o = ((size_t)(b * HH + h) * SS + s) * 32 + hd2;
                    oh[o] = hw;
                    ol[o] = lw;
                }
            }
    }
}

// ---------------------------------------------------------------------------
// Output projection GEMM: C fp32 = AO * WO^T
// ---------------------------------------------------------------------------
__global__ __launch_bounds__(256) void gemm_hmma(
    const __nv_bfloat16* __restrict__ Ah, const __nv_bfloat16* __restrict__ Al,
    const __nv_bfloat16* __restrict__ Bh, const __nv_bfloat16* __restrict__ Bl,
    float* __restrict__ C)
{
    extern __shared__ char gsm[];
    const uint32_t sb = smem_u32(gsm);
    const int tid = threadIdx.x;
    const int bm = blockIdx.y * 128;
    const int bn = blockIdx.x * 128;

    float acc[4][4][4];
#pragma unroll
    for (int i = 0; i < 4; i++)
#pragma unroll
        for (int j = 0; j < 4; j++)
#pragma unroll
            for (int r = 0; r < 4; r++) acc[i][j][r] = 0.f;

    gemm_core(Ah, Al, Bh, Bl, sb, tid, bm, bn, acc);

    const int lane = tid & 31;
    const int wid  = tid >> 5;
    const int wm = (wid & 1) * 64;
    const int wn = (wid >> 1) * 32;
    const int g  = lane >> 2;
    const int t2 = (lane & 3) * 2;
#pragma unroll
    for (int mt = 0; mt < 4; mt++)
#pragma unroll
        for (int nt = 0; nt < 4; nt++) {
            int r0 = bm + wm + mt*16 + g;
            int cc = bn + wn + nt*8 + t2;
            *reinterpret_cast<float2*>(&C[(size_t)r0 * DD + cc]) =
                make_float2(acc[mt][nt][0], acc[mt][nt][1]);
            *reinterpret_cast<float2*>(&C[(size_t)(r0 + 8) * DD + cc]) =
                make_float2(acc[mt][nt][2], acc[mt][nt][3]);
        }
}

// ---------------------------------------------------------------------------
// HMMA causal flash attention, cp.async double-buffered K/V.
// 64q/128-thread body, (128,3) reg cap; dynamic smem 2 stages x 36864 B.
// Stage layout: 4 arrays (Kh, Kl, Vh, Vl) of 64 rows x 72 bf16 (144 B/row).
// Prefetch uses 4 persistent base pointers + fixed per-tile strides.
// Scores pre-scaled by log2(e) -> exp2f softmax.
// Output written as bf16 hi/lo split directly.
// ---------------------------------------------------------------------------
#define SROW  144u
#define SARR  9216u
#define SSTG  36864u
#define ASM_B (2u*SSTG)

__global__ __launch_bounds__(128, 3) void attn_hmma(
    const __nv_bfloat16* __restrict__ Qh, const __nv_bfloat16* __restrict__ Ql,
    const __nv_bfloat16* __restrict__ Kh, const __nv_bfloat16* __restrict__ Kl,
    const __nv_bfloat16* __restrict__ Vth, const __nv_bfloat16* __restrict__ Vtl,
    __nv_bfloat16* __restrict__ AOh, __nv_bfloat16* __restrict__ AOl)
{
    extern __shared__ char smem_dyn[];
    const uint32_t sb = smem_u32(smem_dyn);

    const int bh = blockIdx.y;
    const int b  = bh / HH, h = bh % HH;
    const int qt = gridDim.x - 1 - blockIdx.x;
    const int q0 = qt * 64;
    const int tid  = threadIdx.x;
    const int wid  = tid >> 5;
    const int lane = tid & 31;
    const int lrow = lane & 15;
    const int lcol = (lane >> 4) * 8;
    const int g  = lane >> 2;
    const int tq = lane & 3;

    const uint4* gqh = reinterpret_cast<const uint4*>(Qh);
    const uint4* gql = reinterpret_cast<const uint4*>(Ql);

    // per-thread load slot: row base (tid>>3), column (tid&7); j adds 16 rows
    const int rK = tid >> 3;
    const int cK = tid & 7;
    const uint32_t dOff = (uint32_t)rK * SROW + (uint32_t)cK * 16u;

    const uint4* baseKh = reinterpret_cast<const uint4*>(Kh)
                        + ((size_t)bh * SS + rK) * 8 + cK;
    const uint4* baseKl = reinterpret_cast<const uint4*>(Kl)
                        + ((size_t)bh * SS + rK) * 8 + cK;
    const uint4* baseVh = reinterpret_cast<const uint4*>(Vth)
                        + ((size_t)bh * HD + rK) * (SS/8) + cK;
    const uint4* baseVl = reinterpret_cast<const uint4*>(Vtl)
                        + ((size_t)bh * HD + rK) * (SS/8) + cK;

    auto pf = [&](int k0, uint32_t stbase) {
#pragma unroll
        for (int j = 0; j < 4; j++) {
            uint32_t d = stbase + dOff + (uint32_t)j * (16u * SROW);
            cp16(d,            baseKh + (size_t)k0 * 8 + j * 128);
            cp16(d + SARR,     baseKl + (size_t)k0 * 8 + j * 128);
            cp16(d + 2u*SARR,  baseVh + (k0 >> 3) + j * (16 * (SS/8)));
            cp16(d + 3u*SARR,  baseVl + (k0 >> 3) + j * (16 * (SS/8)));
        }
    };

    // prefetch tile 0 into stage 0
    pf(0, sb);
    asm volatile("cp.async.commit_group;" ::: "memory");

    // stage Q into stage-1 arrays 0 (hi) and 1 (lo), regular stores
#pragma unroll
    for (int j = 0; j < 4; j++) {
        uint32_t d = SSTG + dOff + (uint32_t)j * (16u * SROW);
        *reinterpret_cast<uint4*>(smem_dyn + d) =
            gqh[((size_t)bh * SS + q0 + rK + j*16) * 8 + cK];
        *reinterpret_cast<uint4*>(smem_dyn + d + SARR) =
            gql[((size_t)bh * SS + q0 + rK + j*16) * 8 + cK];
    }
    __syncthreads();

    uint32_t qfh[4][4], qfl[4][4];
#pragma unroll
    for (int kk = 0; kk < 4; kk++) {
        uint32_t ra = SSTG + (uint32_t)(wid*16 + lrow) * SROW
                    + (uint32_t)(kk*16 + lcol) * 2u;
        ldm4(qfh[kk][0], qfh[kk][1], qfh[kk][2], qfh[kk][3], sb + ra);
        ldm4(qfl[kk][0], qfl[kk][1], qfl[kk][2], qfl[kk][3], sb + ra + SARR);
    }
    __syncthreads();   // stage-1 free for tile-1 prefetch

    float ov[8][4];
#pragma unroll
    for (int nt = 0; nt < 8; nt++)
#pragma unroll
        for (int r = 0; r < 4; r++) ov[nt][r] = 0.f;
    float m0 = -1e30f, m1 = -1e30f, l0 = 0.f, l1 = 0.f;

    for (int k0 = 0; k0 <= q0; k0 += 64) {
        const int st = (k0 >> 6) & 1;
        if (k0 + 64 <= q0) {
            pf(k0 + 64, sb + (uint32_t)(st ^ 1) * SSTG);
            asm volatile("cp.async.commit_group;" ::: "memory");
            asm volatile("cp.async.wait_group 1;" ::: "memory");
        } else {
            asm volatile("cp.async.wait_group 0;" ::: "memory");
        }
        __syncthreads();

        const uint32_t bK  = sb + (uint32_t)st * SSTG;
        const uint32_t bKl = bK + SARR;
        const uint32_t bV  = bK + 2u * SARR;
        const uint32_t bVl = bK + 3u * SARR;

        float sc[8][4];
#pragma unroll
        for (int nt = 0; nt < 8; nt++)
#pragma unroll
            for (int r = 0; r < 4; r++) sc[nt][r] = 0.f;

#pragma unroll
        for (int kk = 0; kk < 4; kk++) {
            uint32_t kfh[8][2], kfl[8][2];
#pragma unroll
            for (int np = 0; np < 4; np++) {
                uint32_t rb = (uint32_t)(np*16 + lrow) * SROW
                            + (uint32_t)(kk*16 + lcol) * 2u;
                uint32_t t0, t1, t2, t3;
                ldm4(t0, t1, t2, t3, bK + rb);
                kfh[2*np][0] = t0; kfh[2*np][1] = t2;
                kfh[2*np+1][0] = t1; kfh[2*np+1][1] = t3;
                ldm4(t0, t1, t2, t3, bKl + rb);
                kfl[2*np][0] = t0; kfl[2*np][1] = t2;
                kfl[2*np+1][0] = t1; kfl[2*np+1][1] = t3;
            }
#pragma unroll
            for (int nt = 0; nt < 8; nt++) {
                mma16816(sc[nt], qfh[kk], kfh[nt][0], kfh[nt][1]);
                mma16816(sc[nt], qfh[kk], kfl[nt][0], kfl[nt][1]);
                mma16816(sc[nt], qfl[kk], kfh[nt][0], kfh[nt][1]);
            }
        }

        if (k0 == q0) {
            const int r0 = wid*16 + g, r1 = r0 + 8;
#pragma unroll
            for (int nt = 0; nt < 8; nt++) {
                int key0 = nt*8 + tq*2, key1 = key0 + 1;
                if (key0 > r0) sc[nt][0] = -1e30f;
                if (key1 > r0) sc[nt][1] = -1e30f;
                if (key0 > r1) sc[nt][2] = -1e30f;
                if (key1 > r1) sc[nt][3] = -1e30f;
            }
        }

        float rm0 = -1e30f, rm1 = -1e30f;
#pragma unroll
        for (int nt = 0; nt < 8; nt++) {
            rm0 = fmaxf(rm0, fmaxf(sc[nt][0], sc[nt][1]));
            rm1 = fmaxf(rm1, fmaxf(sc[nt][2], sc[nt][3]));
        }
        rm0 = fmaxf(rm0, __shfl_xor_sync(0xffffffffu, rm0, 1));
        rm0 = fmaxf(rm0, __shfl_xor_sync(0xffffffffu, rm0, 2));
        rm1 = fmaxf(rm1, __shfl_xor_sync(0xffffffffu, rm1, 1));
        rm1 = fmaxf(rm1, __shfl_xor_sync(0xffffffffu, rm1, 2));
        float mn0 = fmaxf(m0, rm0), mn1 = fmaxf(m1, rm1);
        float corr0 = exp2f(m0 - mn0), corr1 = exp2f(m1 - mn1);
        m0 = mn0; m1 = mn1;

        float ps0 = 0.f, ps1 = 0.f;
#pragma unroll
        for (int nt = 0; nt < 8; nt++) {
            sc[nt][0] = exp2f(sc[nt][0] - m0); ps0 += sc[nt][0];
            sc[nt][1] = exp2f(sc[nt][1] - m0); ps0 += sc[nt][1];
            sc[nt][2] = exp2f(sc[nt][2] - m1); ps1 += sc[nt][2];
            sc[nt][3] = exp2f(sc[nt][3] - m1); ps1 += sc[nt][3];
        }
        l0 = l0 * corr0 + ps0;
        l1 = l1 * corr1 + ps1;
#pragma unroll
        for (int nt = 0; nt < 8; nt++) {
            ov[nt][0] *= corr0; ov[nt][1] *= corr0;
            ov[nt][2] *= corr1; ov[nt][3] *= corr1;
        }

        // PV: P packed per-kk (small live set)
#pragma unroll
        for (int kk = 0; kk < 4; kk++) {
            uint32_t pfh[4], pfl[4];
            split2(sc[2*kk  ][0], sc[2*kk  ][1], pfh[0], pfl[0]);
            split2(sc[2*kk  ][2], sc[2*kk  ][3], pfh[1], pfl[1]);
            split2(sc[2*kk+1][0], sc[2*kk+1][1], pfh[2], pfl[2]);
            split2(sc[2*kk+1][2], sc[2*kk+1][3], pfh[3], pfl[3]);

            uint32_t vfh[8][2], vfl[8][2];
#pragma unroll
            for (int np = 0; np < 4; np++) {
                uint32_t rb = (uint32_t)(np*16 + lrow) * SROW
                            + (uint32_t)(kk*16 + lcol) * 2u;
                uint32_t t0, t1, t2, t3;
                ldm4(t0, t1, t2, t3, bV + rb);
                vfh[2*np][0] = t0; vfh[2*np][1] = t2;
                vfh[2*np+1][0] = t1; vfh[2*np+1][1] = t3;
                ldm4(t0, t1, t2, t3, bVl + rb);
                vfl[2*np][0] = t0; vfl[2*np][1] = t2;
                vfl[2*np+1][0] = t1; vfl[2*np+1][1] = t3;
            }
#pragma unroll
            for (int nt = 0; nt < 8; nt++) {
                mma16816(ov[nt], pfh, vfh[nt][0], vfh[nt][1]);
                mma16816(ov[nt], pfh, vfl[nt][0], vfl[nt][1]);
                mma16816(ov[nt], pfl, vfh[nt][0], vfh[nt][1]);
            }
        }
        __syncthreads();
    }

    l0 += __shfl_xor_sync(0xffffffffu, l0, 1);
    l0 += __shfl_xor_sync(0xffffffffu, l0, 2);
    l1 += __shfl_xor_sync(0xffffffffu, l1, 1);
    l1 += __shfl_xor_sync(0xffffffffu, l1, 2);
    float inv0 = 1.f / l0, inv1 = 1.f / l1;

    uint32_t* aoh = reinterpret_cast<uint32_t*>(AOh);
    uint32_t* aol = reinterpret_cast<uint32_t*>(AOl);
    const int r0 = q0 + wid*16 + g;
    const int r1 = r0 + 8;
#pragma unroll
    for (int nt = 0; nt < 8; nt++) {
        int col = nt*8 + tq*2;
        uint32_t hw, lw;
        split2(ov[nt][0] * inv0, ov[nt][1] * inv0, hw, lw);
        size_t o0 = (((size_t)(b * SS + r0) * DD) + h * HD + col) >> 1;
        aoh[o0] = hw; aol[o0] = lw;
        split2(ov[nt][2] * inv1, ov[nt][3] * inv1, hw, lw);
        size_t o1 = (((size_t)(b * SS + r1) * DD) + h * HD + col) >> 1;
        aoh[o1] = hw; aol[o1] = lw;
    }
}

// ---------------------------------------------------------------------------
// Launch
// ---------------------------------------------------------------------------
extern "C" void kernel_launch(void* const* d_in, const int* in_sizes, int n_in,
                              void* d_out, int out_size)
{
    const float* x  = (const float*)d_in[0];
    const float* wq = (const float*)d_in[1];
    const float* wk = (const float*)d_in[2];
    const float* wv = (const float*)d_in[3];
    const float* wo = (const float*)d_in[4];
    const float* fc = (const float*)d_in[5];
    const float* fs = (const float*)d_in[6];
    float* out = (float*)d_out;

    float* v;
    cudaGetSymbolAddress((void**)&v, g_v);

    __nv_bfloat16 *xh, *xl, *aoh, *aol;
    __nv_bfloat16 *wqh, *wql, *wkh, *wkl, *wvh, *wvl, *woh, *wol;
    __nv_bfloat16 *qh, *ql, *kh, *kl, *vth, *vtl;
    cudaGetSymbolAddress((void**)&xh,  g_xh);  cudaGetSymbolAddress((void**)&xl,  g_xl);
    cudaGetSymbolAddress((void**)&aoh, g_aoh); cudaGetSymbolAddress((void**)&aol, g_aol);
    cudaGetSymbolAddress((void**)&wqh, g_wqh); cudaGetSymbolAddress((void**)&wql, g_wql);
    cudaGetSymbolAddress((void**)&wkh, g_wkh); cudaGetSymbolAddress((void**)&wkl, g_wkl);
    cudaGetSymbolAddress((void**)&wvh, g_wvh); cudaGetSymbolAddress((void**)&wvl, g_wvl);
    cudaGetSymbolAddress((void**)&woh, g_woh); cudaGetSymbolAddress((void**)&wol, g_wol);
    cudaGetSymbolAddress((void**)&qh,  g_qh);  cudaGetSymbolAddress((void**)&ql,  g_ql);
    cudaGetSymbolAddress((void**)&kh,  g_kh);  cudaGetSymbolAddress((void**)&kl,  g_kl);
    cudaGetSymbolAddress((void**)&vth, g_vth); cudaGetSymbolAddress((void**)&vtl, g_vtl);

    cudaFuncSetAttribute(gemm_qkv,
                         cudaFuncAttributeMaxDynamicSharedMemorySize, GSM_B);
    cudaFuncSetAttribute(gemm_hmma,
                         cudaFuncAttributeMaxDynamicSharedMemorySize, GSM_B);
    cudaFuncSetAttribute(attn_hmma,
                         cudaFuncAttributeMaxDynamicSharedMemorySize, ASM_B);

    const int NX4 = MM * DD / 4;
    const int NW4 = DD * DD / 4;
    cvt_hilo<<<(NX4 + 255)/256, 256>>>(x, xh, xl, NX4);
    dim3 gw((NW4 + 255)/256, 4);
    cvt_hilo_w<<<gw, 256>>>(wq, wk, wv, wo,
                            wqh, wql, wkh, wkl, wvh, wvl, woh, wol);

    dim3 gq(DD / 128, MM / 128, 3);
    gemm_qkv<<<gq, 256, GSM_B>>>(xh, xl, wqh, wql, wkh, wkl, wvh, wvl,
                                 qh, ql, kh, kl, v, fc, fs);

    dim3 gt(SS / 64, BB * HH);
    cvt_transpose_v<<<gt, 256>>>(v, vth, vtl);

    dim3 ga(SS / 64, BB * HH);
    attn_hmma<<<ga, 128, ASM_B>>>(qh, ql, kh, kl, vth, vtl, aoh, aol);

    dim3 gg(DD / 128, MM / 128);
    gemm_hmma<<<gg, 256, GSM_B>>>(aoh, aol, woh, wol, out);
}

// round 17
// speedup vs baseline: 1.4178x; 1.4000x over previous
#include <cuda_runtime.h>
#include <cuda_fp16.h>
#include <cstdint>
#include <cstddef>

// Problem constants
#define BB   2
#define SS   2048
#define DD   1024
#define HH   16
#define HD   64
#define MM   (BB*SS)

// fp32 scratch for V
__device__ float g_v [BB*SS*DD];

// fp16 scratch: A-side operands hi-only; B-side operands hi+lo
__device__ __half g_xh [MM*DD];
__device__ __half g_aoh[MM*DD];
__device__ __half g_wqh[DD*DD], g_wql[DD*DD];
__device__ __half g_wkh[DD*DD], g_wkl[DD*DD];
__device__ __half g_wvh[DD*DD], g_wvl[DD*DD];
__device__ __half g_woh[DD*DD], g_wol[DD*DD];

// attention operands: q hi-only [B,H,S,HD]; k hi+lo [B,H,S,HD]; v hi+lo [B,H,HD,S]
__device__ __half g_qh [MM*DD];
__device__ __half g_kh [MM*DD], g_kl [MM*DD];
__device__ __half g_vth[MM*DD], g_vtl[MM*DD];

// ---------------------------------------------------------------------------
// helpers
// ---------------------------------------------------------------------------
__device__ __forceinline__ uint32_t smem_u32(const void* p) {
    uint32_t a;
    asm("{ .reg .u64 t; cvta.to.shared.u64 t, %1; cvt.u32.u64 %0, t; }"
        : "=r"(a) : "l"(p));
    return a;
}
__device__ __forceinline__ void ldm4(uint32_t& r0, uint32_t& r1, uint32_t& r2,
                                     uint32_t& r3, uint32_t addr) {
    asm volatile("ldmatrix.sync.aligned.m8n8.x4.shared.b16 {%0,%1,%2,%3}, [%4];"
                 : "=r"(r0), "=r"(r1), "=r"(r2), "=r"(r3) : "r"(addr));
}
__device__ __forceinline__ void mma16816(float* c, const uint32_t* a,
                                         uint32_t b0, uint32_t b1) {
    asm volatile(
        "mma.sync.aligned.m16n8k16.row.col.f32.f16.f16.f32 "
        "{%0,%1,%2,%3}, {%4,%5,%6,%7}, {%8,%9}, {%0,%1,%2,%3};"
        : "+f"(c[0]), "+f"(c[1]), "+f"(c[2]), "+f"(c[3])
        : "r"(a[0]), "r"(a[1]), "r"(a[2]), "r"(a[3]), "r"(b0), "r"(b1));
}
__device__ __forceinline__ uint32_t pack2h(float f0, float f1) {
    __half2 h = __floats2half2_rn(f0, f1);
    return *reinterpret_cast<uint32_t*>(&h);
}
__device__ __forceinline__ void split2h(float f0, float f1,
                                        uint32_t& hw, uint32_t& lw) {
    __half h0 = __float2half_rn(f0);
    __half h1 = __float2half_rn(f1);
    __half l0 = __float2half_rn(f0 - __half2float(h0));
    __half l1 = __float2half_rn(f1 - __half2float(h1));
    hw = (uint32_t)__half_as_ushort(h0) | ((uint32_t)__half_as_ushort(h1) << 16);
    lw = (uint32_t)__half_as_ushort(l0) | ((uint32_t)__half_as_ushort(l1) << 16);
}
__device__ __forceinline__ void cp16(uint32_t dst, const void* src) {
    asm volatile("cp.async.cg.shared.global [%0], [%1], 16;"
                 :: "r"(dst), "l"(src));
}

// ---------------------------------------------------------------------------
// fp32 -> fp16 hi-only conversion (flat, vectorized by 4)
// ---------------------------------------------------------------------------
__global__ void cvt_h(const float* __restrict__ in,
                      __half* __restrict__ hi, int n4)
{
    int i = blockIdx.x * blockDim.x + threadIdx.x;
    if (i >= n4) return;
    float4 v = reinterpret_cast<const float4*>(in)[i];
    reinterpret_cast<uint2*>(hi)[i] =
        make_uint2(pack2h(v.x, v.y), pack2h(v.z, v.w));
}

// Merged hi/lo conversion of the 4 weight matrices (blockIdx.y selects matrix).
__global__ void cvt_hilo_w(
    const float* __restrict__ w0, const float* __restrict__ w1,
    const float* __restrict__ w2, const float* __restrict__ w3,
    __half* __restrict__ h0p, __half* __restrict__ l0p,
    __half* __restrict__ h1p, __half* __restrict__ l1p,
    __half* __restrict__ h2p, __half* __restrict__ l2p,
    __half* __restrict__ h3p, __half* __restrict__ l3p)
{
    const int n4 = DD * DD / 4;
    int i = blockIdx.x * blockDim.x + threadIdx.x;
    if (i >= n4) return;
    int z = blockIdx.y;
    const float* in = (z == 0) ? w0 : (z == 1) ? w1 : (z == 2) ? w2 : w3;
    __half* hi = (z == 0) ? h0p : (z == 1) ? h1p : (z == 2) ? h2p : h3p;
    __half* lo = (z == 0) ? l0p : (z == 1) ? l1p : (z == 2) ? l2p : l3p;
    float4 v = reinterpret_cast<const float4*>(in)[i];
    uint32_t hw0, lw0, hw1, lw1;
    split2h(v.x, v.y, hw0, lw0);
    split2h(v.z, v.w, hw1, lw1);
    reinterpret_cast<uint2*>(hi)[i] = make_uint2(hw0, hw1);
    reinterpret_cast<uint2*>(lo)[i] = make_uint2(lw0, lw1);
}

// ---------------------------------------------------------------------------
// fp32 v [B,S,H,HD] -> fp16 hi/lo vt [B,H,HD,S] (transposed, coalesced)
// ---------------------------------------------------------------------------
__global__ __launch_bounds__(256) void cvt_transpose_v(
    const float* __restrict__ src,
    __half* __restrict__ hi,
    __half* __restrict__ lo)
{
    __shared__ __half th[64][66], tl[64][66];
    const int bh = blockIdx.y;
    const int b  = bh / HH, h = bh % HH;
    const int s0 = blockIdx.x * 64;
    const int tid = threadIdx.x;

#pragma unroll
    for (int it = 0; it < 8; it++) {
        int i = tid + it * 256;
        int d2 = i & 31, sl = i >> 5;
        float2 v = reinterpret_cast<const float2*>(src)
                       [((size_t)(b * SS + s0 + sl) * HH + h) * 32 + d2];
        __half h0 = __float2half_rn(v.x);
        __half h1 = __float2half_rn(v.y);
        th[d2*2  ][sl] = h0;
        th[d2*2+1][sl] = h1;
        tl[d2*2  ][sl] = __float2half_rn(v.x - __half2float(h0));
        tl[d2*2+1][sl] = __float2half_rn(v.y - __half2float(h1));
    }
    __syncthreads();
#pragma unroll
    for (int it = 0; it < 8; it++) {
        int i = tid + it * 256;
        int su = i & 31, d = i >> 5;
        uint32_t hw = (uint32_t)__half_as_ushort(th[d][su*2]) |
                      ((uint32_t)__half_as_ushort(th[d][su*2+1]) << 16);
        uint32_t lw = (uint32_t)__half_as_ushort(tl[d][su*2]) |
                      ((uint32_t)__half_as_ushort(tl[d][su*2+1]) << 16);
        size_t o = ((size_t)(bh * HD + d) * SS + s0) / 2 + su;
        reinterpret_cast<uint32_t*>(hi)[o] = hw;
        reinterpret_cast<uint32_t*>(lo)[o] = lw;
    }
}

// ---------------------------------------------------------------------------
// Shared GEMM mainloop (NT): acc += A[bm:+128] x W[bn:+128]^T over K=DD.
// fp16 2-term: A hi-only; B hi+lo.  cp.async 2-stage pipeline.
// smem: 2 stages x 3 arrays (Ah, Bh, Bl) x 10240 B = 61440 B.
// ---------------------------------------------------------------------------
#define GROW_B   80u
#define GARR_B   10240u
#define GSM_B    (2u*3u*GARR_B)

__device__ __forceinline__ void gemm_core(
    const __half* __restrict__ Ah,
    const __half* __restrict__ Bh, const __half* __restrict__ Bl,
    uint32_t sb, int tid, int bm, int bn, float (&acc)[4][4][4])
{
    const int wid  = tid >> 5;
    const int lane = tid & 31;
    const int wm = (wid & 1) * 64;
    const int wn = (wid >> 1) * 32;
    const int lrow = lane & 15;
    const int lcol = (lane >> 4) * 8;

    auto prefetch = [&](int st, int k0) {
#pragma unroll
        for (int p = 0; p < 6; p++) {
            int idx = tid + p * 256;        // 0..1535
            int arr = idx >> 9;             // 0:Ah 1:Bh 2:Bl
            int sub = idx & 511;
            int r   = sub >> 2;
            int c4  = sub & 3;
            size_t off;
            if (arr == 0) off = (size_t)(bm + r) * DD + k0 + c4 * 8;
            else          off = (size_t)(bn + r) * DD + k0 + c4 * 8;
            const __half* gp = (arr == 0 ? Ah : arr == 1 ? Bh : Bl) + off;
            uint32_t dst = sb + (uint32_t)(st * 3 + arr) * GARR_B
                         + (uint32_t)r * GROW_B + (uint32_t)c4 * 16u;
            cp16(dst, gp);
        }
    };

    prefetch(0, 0);
    asm volatile("cp.async.commit_group;" ::: "memory");

    int st = 0;
    for (int k0 = 0; k0 < DD; k0 += 32) {
        if (k0 + 32 < DD) {
            prefetch(st ^ 1, k0 + 32);
            asm volatile("cp.async.commit_group;" ::: "memory");
            asm volatile("cp.async.wait_group 1;" ::: "memory");
        } else {
            asm volatile("cp.async.wait_group 0;" ::: "memory");
        }
        __syncthreads();

        const uint32_t bAh = sb + (uint32_t)(st * 3 + 0) * GARR_B;
        const uint32_t bBh = sb + (uint32_t)(st * 3 + 1) * GARR_B;
        const uint32_t bBl = sb + (uint32_t)(st * 3 + 2) * GARR_B;

#pragma unroll
        for (int kk = 0; kk < 32; kk += 16) {
            uint32_t ah[4][4], bh[4][2], bl[4][2];
#pragma unroll
            for (int mt = 0; mt < 4; mt++) {
                uint32_t ra = (uint32_t)(wm + mt*16 + lrow) * GROW_B
                            + (uint32_t)(kk + lcol) * 2u;
                ldm4(ah[mt][0], ah[mt][1], ah[mt][2], ah[mt][3], bAh + ra);
            }
#pragma unroll
            for (int np = 0; np < 2; np++) {
                uint32_t rb = (uint32_t)(wn + np*16 + lrow) * GROW_B
                            + (uint32_t)(kk + lcol) * 2u;
                uint32_t t0, t1, t2, t3;
                ldm4(t0, t1, t2, t3, bBh + rb);
                bh[2*np][0] = t0; bh[2*np][1] = t2;
                bh[2*np+1][0] = t1; bh[2*np+1][1] = t3;
                ldm4(t0, t1, t2, t3, bBl + rb);
                bl[2*np][0] = t0; bl[2*np][1] = t2;
                bl[2*np+1][0] = t1; bl[2*np+1][1] = t3;
            }
#pragma unroll
            for (int mt = 0; mt < 4; mt++)
#pragma unroll
                for (int nt = 0; nt < 4; nt++) {
                    mma16816(acc[mt][nt], ah[mt], bh[nt][0], bh[nt][1]);
                    mma16816(acc[mt][nt], ah[mt], bl[nt][0], bl[nt][1]);
                }
        }
        __syncthreads();
        st ^= 1;
    }
}

// ---------------------------------------------------------------------------
// Fused QKV projection: blockIdx.z selects {Q, K, V}.
// Q: rope + scale -> fp16 hi [B,H,S,HD].  K: rope -> fp16 hi+lo [B,H,S,HD].
// V: fp32 [B,S,H,HD].
// ---------------------------------------------------------------------------
#define QSCALE 0.1803368801111355f   // (1/8) * log2(e)

__global__ __launch_bounds__(256) void gemm_qkv(
    const __half* __restrict__ Xh,
    const __half* __restrict__ Wqh, const __half* __restrict__ Wql,
    const __half* __restrict__ Wkh, const __half* __restrict__ Wkl,
    const __half* __restrict__ Wvh, const __half* __restrict__ Wvl,
    __half* __restrict__ Qh,
    __half* __restrict__ Kh, __half* __restrict__ Kl,
    float* __restrict__ V,
    const float* __restrict__ fc, const float* __restrict__ fs)
{
    extern __shared__ char gsm[];
    const uint32_t sb = smem_u32(gsm);
    const int tid = threadIdx.x;
    const int bm = blockIdx.y * 128;
    const int bn = blockIdx.x * 128;
    const int z  = blockIdx.z;

    const __half* Bh = (z == 0) ? Wqh : (z == 1) ? Wkh : Wvh;
    const __half* Bl = (z == 0) ? Wql : (z == 1) ? Wkl : Wvl;

    float acc[4][4][4];
#pragma unroll
    for (int i = 0; i < 4; i++)
#pragma unroll
        for (int j = 0; j < 4; j++)
#pragma unroll
            for (int r = 0; r < 4; r++) acc[i][j][r] = 0.f;

    gemm_core(Xh, Bh, Bl, sb, tid, bm, bn, acc);

    const int lane = tid & 31;
    const int wid  = tid >> 5;
    const int wm = (wid & 1) * 64;
    const int wn = (wid >> 1) * 32;
    const int g  = lane >> 2;
    const int t2 = (lane & 3) * 2;

    if (z == 2) {
#pragma unroll
        for (int mt = 0; mt < 4; mt++)
#pragma unroll
            for (int nt = 0; nt < 4; nt++) {
                int r0 = bm + wm + mt*16 + g;
                int cc = bn + wn + nt*8 + t2;
                *reinterpret_cast<float2*>(&V[(size_t)r0 * DD + cc]) =
                    make_float2(acc[mt][nt][0], acc[mt][nt][1]);
                *reinterpret_cast<float2*>(&V[(size_t)(r0 + 8) * DD + cc]) =
                    make_float2(acc[mt][nt][2], acc[mt][nt][3]);
            }
    } else {
        const float scale = (z == 0) ? QSCALE : 1.0f;
        uint32_t* oh = reinterpret_cast<uint32_t*>(z == 0 ? Qh : Kh);
        uint32_t* ol = reinterpret_cast<uint32_t*>(Kl);
#pragma unroll
        for (int mt = 0; mt < 4; mt++)
#pragma unroll
            for (int nt = 0; nt < 4; nt++) {
                int cc  = bn + wn + nt*8 + t2;
                int h   = cc >> 6;
                int hd2 = (cc & 63) >> 1;
#pragma unroll
                for (int rr = 0; rr < 2; rr++) {
                    int row = bm + wm + mt*16 + g + rr*8;
                    int s = row & (SS - 1);
                    int b = row >> 11;
                    float c  = fc[s * 32 + hd2];
                    float sn = fs[s * 32 + hd2];
                    float a0 = acc[mt][nt][rr*2 + 0];
                    float a1 = acc[mt][nt][rr*2 + 1];
                    float r0v = (a0 * c - a1 * sn) * scale;
                    float r1v = (a0 * sn + a1 * c) * scale;
                    size_t o = ((size_t)(b * HH + h) * SS + s) * 32 + hd2;
                    if (z == 0) {
                        oh[o] = pack2h(r0v, r1v);
                    } else {
                        uint32_t hw, lw;
                        split2h(r0v, r1v, hw, lw);
                        oh[o] = hw;
                        ol[o] = lw;
                    }
                }
            }
    }
}

// ---------------------------------------------------------------------------
// Output projection GEMM: C fp32 = AO(hi) * (WOh + WOl)^T
// ---------------------------------------------------------------------------
__global__ __launch_bounds__(256) void gemm_hmma(
    const __half* __restrict__ Ah,
    const __half* __restrict__ Bh, const __half* __restrict__ Bl,
    float* __restrict__ C)
{
    extern __shared__ char gsm[];
    const uint32_t sb = smem_u32(gsm);
    const int tid = threadIdx.x;
    const int bm = blockIdx.y * 128;
    const int bn = blockIdx.x * 128;

    float acc[4][4][4];
#pragma unroll
    for (int i = 0; i < 4; i++)
#pragma unroll
        for (int j = 0; j < 4; j++)
#pragma unroll
            for (int r = 0; r < 4; r++) acc[i][j][r] = 0.f;

    gemm_core(Ah, Bh, Bl, sb, tid, bm, bn, acc);

    const int lane = tid & 31;
    const int wid  = tid >> 5;
    const int wm = (wid & 1) * 64;
    const int wn = (wid >> 1) * 32;
    const int g  = lane >> 2;
    const int t2 = (lane & 3) * 2;
#pragma unroll
    for (int mt = 0; mt < 4; mt++)
#pragma unroll
        for (int nt = 0; nt < 4; nt++) {
            int r0 = bm + wm + mt*16 + g;
            int cc = bn + wn + nt*8 + t2;
            *reinterpret_cast<float2*>(&C[(size_t)r0 * DD + cc]) =
                make_float2(acc[mt][nt][0], acc[mt][nt][1]);
            *reinterpret_cast<float2*>(&C[(size_t)(r0 + 8) * DD + cc]) =
                make_float2(acc[mt][nt][2], acc[mt][nt][3]);
        }
}

// ---------------------------------------------------------------------------
// HMMA causal flash attention, fp16 2-term, cp.async double-buffered K/V.
// 64q/128-thread body, (128,3) reg cap; dynamic smem 2 stages x 36864 B.
// Stage layout: 4 arrays (Kh, Kl, Vh, Vl) of 64 rows x 72 fp16 (144 B/row).
// Q hi-only; scores = Qh*(Kh+Kl); PV = Ph*(Vh+Vl).
// Scores pre-scaled by log2(e) -> exp2f softmax.  Output fp16 hi [B,S,D].
// ---------------------------------------------------------------------------
#define SROW  144u
#define SARR  9216u
#define SSTG  36864u
#define ASM_B (2u*SSTG)

__global__ __launch_bounds__(128, 3) void attn_hmma(
    const __half* __restrict__ Qh,
    const __half* __restrict__ Kh, const __half* __restrict__ Kl,
    const __half* __restrict__ Vth, const __half* __restrict__ Vtl,
    __half* __restrict__ AOh)
{
    extern __shared__ char smem_dyn[];
    const uint32_t sb = smem_u32(smem_dyn);

    const int bh = blockIdx.y;
    const int b  = bh / HH, h = bh % HH;
    const int qt = gridDim.x - 1 - blockIdx.x;
    const int q0 = qt * 64;
    const int tid  = threadIdx.x;
    const int wid  = tid >> 5;
    const int lane = tid & 31;
    const int lrow = lane & 15;
    const int lcol = (lane >> 4) * 8;
    const int g  = lane >> 2;
    const int tq = lane & 3;

    const uint4* gqh = reinterpret_cast<const uint4*>(Qh);

    const int rK = tid >> 3;
    const int cK = tid & 7;
    const uint32_t dOff = (uint32_t)rK * SROW + (uint32_t)cK * 16u;

    const uint4* baseKh = reinterpret_cast<const uint4*>(Kh)
                        + ((size_t)bh * SS + rK) * 8 + cK;
    const uint4* baseKl = reinterpret_cast<const uint4*>(Kl)
                        + ((size_t)bh * SS + rK) * 8 + cK;
    const uint4* baseVh = reinterpret_cast<const uint4*>(Vth)
                        + ((size_t)bh * HD + rK) * (SS/8) + cK;
    const uint4* baseVl = reinterpret_cast<const uint4*>(Vtl)
                        + ((size_t)bh * HD + rK) * (SS/8) + cK;

    auto pf = [&](int k0, uint32_t stbase) {
#pragma unroll
        for (int j = 0; j < 4; j++) {
            uint32_t d = stbase + dOff + (uint32_t)j * (16u * SROW);
            cp16(d,            baseKh + (size_t)k0 * 8 + j * 128);
            cp16(d + SARR,     baseKl + (size_t)k0 * 8 + j * 128);
            cp16(d + 2u*SARR,  baseVh + (k0 >> 3) + j * (16 * (SS/8)));
            cp16(d + 3u*SARR,  baseVl + (k0 >> 3) + j * (16 * (SS/8)));
        }
    };

    pf(0, sb);
    asm volatile("cp.async.commit_group;" ::: "memory");

    // stage Q (hi only) into stage-1 array 0
#pragma unroll
    for (int j = 0; j < 4; j++) {
        uint32_t d = SSTG + dOff + (uint32_t)j * (16u * SROW);
        *reinterpret_cast<uint4*>(smem_dyn + d) =
            gqh[((size_t)bh * SS + q0 + rK + j*16) * 8 + cK];
    }
    __syncthreads();

    uint32_t qfh[4][4];
#pragma unroll
    for (int kk = 0; kk < 4; kk++) {
        uint32_t ra = SSTG + (uint32_t)(wid*16 + lrow) * SROW
                    + (uint32_t)(kk*16 + lcol) * 2u;
        ldm4(qfh[kk][0], qfh[kk][1], qfh[kk][2], qfh[kk][3], sb + ra);
    }
    __syncthreads();

    float ov[8][4];
#pragma unroll
    for (int nt = 0; nt < 8; nt++)
#pragma unroll
        for (int r = 0; r < 4; r++) ov[nt][r] = 0.f;
    float m0 = -1e30f, m1 = -1e30f, l0 = 0.f, l1 = 0.f;

    for (int k0 = 0; k0 <= q0; k0 += 64) {
        const int st = (k0 >> 6) & 1;
        if (k0 + 64 <= q0) {
            pf(k0 + 64, sb + (uint32_t)(st ^ 1) * SSTG);
            asm volatile("cp.async.commit_group;" ::: "memory");
            asm volatile("cp.async.wait_group 1;" ::: "memory");
        } else {
            asm volatile("cp.async.wait_group 0;" ::: "memory");
        }
        __syncthreads();

        const uint32_t bK  = sb + (uint32_t)st * SSTG;
        const uint32_t bKl = bK + SARR;
        const uint32_t bV  = bK + 2u * SARR;
        const uint32_t bVl = bK + 3u * SARR;

        float sc[8][4];
#pragma unroll
        for (int nt = 0; nt < 8; nt++)
#pragma unroll
            for (int r = 0; r < 4; r++) sc[nt][r] = 0.f;

#pragma unroll
        for (int kk = 0; kk < 4; kk++) {
            uint32_t kfh[8][2], kfl[8][2];
#pragma unroll
            for (int np = 0; np < 4; np++) {
                uint32_t rb = (uint32_t)(np*16 + lrow) * SROW
                            + (uint32_t)(kk*16 + lcol) * 2u;
                uint32_t t0, t1, t2, t3;
                ldm4(t0, t1, t2, t3, bK + rb);
                kfh[2*np][0] = t0; kfh[2*np][1] = t2;
                kfh[2*np+1][0] = t1; kfh[2*np+1][1] = t3;
                ldm4(t0, t1, t2, t3, bKl + rb);
                kfl[2*np][0] = t0; kfl[2*np][1] = t2;
                kfl[2*np+1][0] = t1; kfl[2*np+1][1] = t3;
            }
#pragma unroll
            for (int nt = 0; nt < 8; nt++) {
                mma16816(sc[nt], qfh[kk], kfh[nt][0], kfh[nt][1]);
                mma16816(sc[nt], qfh[kk], kfl[nt][0], kfl[nt][1]);
            }
        }

        if (k0 == q0) {
            const int r0 = wid*16 + g, r1 = r0 + 8;
#pragma unroll
            for (int nt = 0; nt < 8; nt++) {
                int key0 = nt*8 + tq*2, key1 = key0 + 1;
                if (key0 > r0) sc[nt][0] = -1e30f;
                if (key1 > r0) sc[nt][1] = -1e30f;
                if (key0 > r1) sc[nt][2] = -1e30f;
                if (key1 > r1) sc[nt][3] = -1e30f;
            }
        }

        float rm0 = -1e30f, rm1 = -1e30f;
#pragma unroll
        for (int nt = 0; nt < 8; nt++) {
            rm0 = fmaxf(rm0, fmaxf(sc[nt][0], sc[nt][1]));
            rm1 = fmaxf(rm1, fmaxf(sc[nt][2], sc[nt][3]));
        }
        rm0 = fmaxf(rm0, __shfl_xor_sync(0xffffffffu, rm0, 1));
        rm0 = fmaxf(rm0, __shfl_xor_sync(0xffffffffu, rm0, 2));
        rm1 = fmaxf(rm1, __shfl_xor_sync(0xffffffffu, rm1, 1));
        rm1 = fmaxf(rm1, __shfl_xor_sync(0xffffffffu, rm1, 2));
        float mn0 = fmaxf(m0, rm0), mn1 = fmaxf(m1, rm1);
        float corr0 = exp2f(m0 - mn0), corr1 = exp2f(m1 - mn1);
        m0 = mn0; m1 = mn1;

        float ps0 = 0.f, ps1 = 0.f;
#pragma unroll
        for (int nt = 0; nt < 8; nt++) {
            sc[nt][0] = exp2f(sc[nt][0] - m0); ps0 += sc[nt][0];
            sc[nt][1] = exp2f(sc[nt][1] - m0); ps0 += sc[nt][1];
            sc[nt][2] = exp2f(sc[nt][2] - m1); ps1 += sc[nt][2];
            sc[nt][3] = exp2f(sc[nt][3] - m1); ps1 += sc[nt][3];
        }
        l0 = l0 * corr0 + ps0;
        l1 = l1 * corr1 + ps1;
#pragma unroll
        for (int nt = 0; nt < 8; nt++) {
            ov[nt][0] *= corr0; ov[nt][1] *= corr0;
            ov[nt][2] *= corr1; ov[nt][3] *= corr1;
        }

        // PV: P fp16 hi-only, packed per-kk
#pragma unroll
        for (int kk = 0; kk < 4; kk++) {
            uint32_t pfh[4];
            pfh[0] = pack2h(sc[2*kk  ][0], sc[2*kk  ][1]);
            pfh[1] = pack2h(sc[2*kk  ][2], sc[2*kk  ][3]);
            pfh[2] = pack2h(sc[2*kk+1][0], sc[2*kk+1][1]);
            pfh[3] = pack2h(sc[2*kk+1][2], sc[2*kk+1][3]);

            uint32_t vfh[8][2], vfl[8][2];
#pragma unroll
            for (int np = 0; np < 4; np++) {
                uint32_t rb = (uint32_t)(np*16 + lrow) * SROW
                            + (uint32_t)(kk*16 + lcol) * 2u;
                uint32_t t0, t1, t2, t3;
                ldm4(t0, t1, t2, t3, bV + rb);
                vfh[2*np][0] = t0; vfh[2*np][1] = t2;
                vfh[2*np+1][0] = t1; vfh[2*np+1][1] = t3;
                ldm4(t0, t1, t2, t3, bVl + rb);
                vfl[2*np][0] = t0; vfl[2*np][1] = t2;
                vfl[2*np+1][0] = t1; vfl[2*np+1][1] = t3;
            }
#pragma unroll
            for (int nt = 0; nt < 8; nt++) {
                mma16816(ov[nt], pfh, vfh[nt][0], vfh[nt][1]);
                mma16816(ov[nt], pfh, vfl[nt][0], vfl[nt][1]);
            }
        }
        __syncthreads();
    }

    l0 += __shfl_xor_sync(0xffffffffu, l0, 1);
    l0 += __shfl_xor_sync(0xffffffffu, l0, 2);
    l1 += __shfl_xor_sync(0xffffffffu, l1, 1);
    l1 += __shfl_xor_sync(0xffffffffu, l1, 2);
    float inv0 = 1.f / l0, inv1 = 1.f / l1;

    uint32_t* aoh = reinterpret_cast<uint32_t*>(AOh);
    const int r0 = q0 + wid*16 + g;
    const int r1 = r0 + 8;
#pragma unroll
    for (int nt = 0; nt < 8; nt++) {
        int col = nt*8 + tq*2;
        size_t o0 = (((size_t)(b * SS + r0) * DD) + h * HD + col) >> 1;
        aoh[o0] = pack2h(ov[nt][0] * inv0, ov[nt][1] * inv0);
        size_t o1 = (((size_t)(b * SS + r1) * DD) + h * HD + col) >> 1;
        aoh[o1] = pack2h(ov[nt][2] * inv1, ov[nt][3] * inv1);
    }
}

// ---------------------------------------------------------------------------
// Launch
// ---------------------------------------------------------------------------
extern "C" void kernel_launch(void* const* d_in, const int* in_sizes, int n_in,
                              void* d_out, int out_size)
{
    const float* x  = (const float*)d_in[0];
    const float* wq = (const float*)d_in[1];
    const float* wk = (const float*)d_in[2];
    const float* wv = (const float*)d_in[3];
    const float* wo = (const float*)d_in[4];
    const float* fc = (const float*)d_in[5];
    const float* fs = (const float*)d_in[6];
    float* out = (float*)d_out;

    float* v;
    cudaGetSymbolAddress((void**)&v, g_v);

    __half *xh, *aoh;
    __half *wqh, *wql, *wkh, *wkl, *wvh, *wvl, *woh, *wol;
    __half *qh, *kh, *kl, *vth, *vtl;
    cudaGetSymbolAddress((void**)&xh,  g_xh);
    cudaGetSymbolAddress((void**)&aoh, g_aoh);
    cudaGetSymbolAddress((void**)&wqh, g_wqh); cudaGetSymbolAddress((void**)&wql, g_wql);
    cudaGetSymbolAddress((void**)&wkh, g_wkh); cudaGetSymbolAddress((void**)&wkl, g_wkl);
    cudaGetSymbolAddress((void**)&wvh, g_wvh); cudaGetSymbolAddress((void**)&wvl, g_wvl);
    cudaGetSymbolAddress((void**)&woh, g_woh); cudaGetSymbolAddress((void**)&wol, g_wol);
    cudaGetSymbolAddress((void**)&qh,  g_qh);
    cudaGetSymbolAddress((void**)&kh,  g_kh);  cudaGetSymbolAddress((void**)&kl,  g_kl);
    cudaGetSymbolAddress((void**)&vth, g_vth); cudaGetSymbolAddress((void**)&vtl, g_vtl);

    cudaFuncSetAttribute(gemm_qkv,
                         cudaFuncAttributeMaxDynamicSharedMemorySize, GSM_B);
    cudaFuncSetAttribute(gemm_hmma,
                         cudaFuncAttributeMaxDynamicSharedMemorySize, GSM_B);
    cudaFuncSetAttribute(attn_hmma,
                         cudaFuncAttributeMaxDynamicSharedMemorySize, ASM_B);

    const int NX4 = MM * DD / 4;
    const int NW4 = DD * DD / 4;
    cvt_h<<<(NX4 + 255)/256, 256>>>(x, xh, NX4);
    dim3 gw((NW4 + 255)/256, 4);
    cvt_hilo_w<<<gw, 256>>>(wq, wk, wv, wo,
                            wqh, wql, wkh, wkl, wvh, wvl, woh, wol);

    dim3 gq(DD / 128, MM / 128, 3);
    gemm_qkv<<<gq, 256, GSM_B>>>(xh, wqh, wql, wkh, wkl, wvh, wvl,
                                 qh, kh, kl, v, fc, fs);

    dim3 gt(SS / 64, BB * HH);
    cvt_transpose_v<<<gt, 256>>>(v, vth, vtl);

    dim3 ga(SS / 64, BB * HH);
    attn_hmma<<<ga, 128, ASM_B>>>(qh, kh, kl, vth, vtl, aoh);

    dim3 gg(DD / 128, MM / 128);
    gemm_hmma<<<gg, 256, GSM_B>>>(aoh, woh, wol, out);
}